// round 6
// baseline (speedup 1.0000x reference)
#include <cuda_runtime.h>
#include <cuda_bf16.h>
#include <math.h>

// WaveletAttention: out = x * sigmoid(relu(mean(dwt2_ll(x)) @ W1^T) @ W2^T)
// x [8,256,256,256] f32 (512 MB), W1 [16,256], W2 [256,16].
//
// mean(dwt2_ll(x)) == (1/135^2) * sum_{i,j} w[i]*w[j]*x[b,c,i,j]  (linear +
// separable), w = fixed 256-weight vector from db8 dec_lo, symmetric pad.
//
// R6: persistent kernel, strict per-batch phases (the only scheme where L2
// reuse measured real: R4 hit 1.10 GB DRAM):
//   reduce x[b] (ldcg -> L2)  |grid barrier|  FC + scale x[b] (ldcs hits L2,
//   stcs writes)  -> roll straight into reduce(b+1).
// R4's deficit was phase utilization, not traffic. Fixes: 888 blocks (6/SM),
// sync-free warp-atomic reduction, 8-row chunks (~9 chunks/block, ~10% skew).

#define PLANE4   16384u        // float4 per 256x256 plane
#define NBC      2048
#define INV_MEAN (1.0f/(135.0f*135.0f))

#define GRID_G   888           // 6 blocks/SM * 148 SMs, all co-resident
#define NCH      8192          // 8-row chunks per batch (256 planes * 32)

__device__ float g_yraw[NBC];
__device__ int   g_bar_count;
__device__ int   g_bar_phase;

// pywt db8 dec_lo, 16 taps
__constant__ float c_f[16] = {
    -0.00011747678400228192f, 0.0006754494059985568f, -0.0003917403729959771f,
    -0.00487035299301066f, 0.008746094047015655f, 0.013981027917015516f,
    -0.04408825393106472f, -0.01736930100202211f, 0.128747426620186f,
    0.00047248457399797254f, -0.2840155429624281f, -0.015829105256023893f,
    0.5853546836548691f, 0.6756307362980128f, 0.3128715909144659f,
    0.05441584224308161f
};

__device__ __forceinline__ float wcontrib(int q) {
    float s = 0.f;
#pragma unroll
    for (int k = 0; k < 16; ++k) {
        int qk = q + k;
        bool ok = ((qk & 1) == 0) && (qk >= 16) && (qk <= 284);
        s += ok ? c_f[k] : 0.f;
    }
    return s;
}
__device__ __forceinline__ float weight_at(int i) {
    return wcontrib(i + 15) + wcontrib(14 - i) + wcontrib(526 - i);
}

__global__ void init_kernel() {
    int i = blockIdx.x * blockDim.x + threadIdx.x;
    if (i < NBC) g_yraw[i] = 0.f;
    if (i == 0) { g_bar_count = 0; g_bar_phase = 0; }
}

__global__ void __launch_bounds__(256, 6)
fused_kernel(const float* __restrict__ x, float* __restrict__ out,
             const float* __restrict__ W1, const float* __restrict__ W2) {
    __shared__ float sw[256];
    __shared__ float red[256];
    __shared__ float sh_h[16];

    const int t = threadIdx.x;
    const int bid = blockIdx.x;

    sw[t] = weight_at(t);
    __syncthreads();

    // chunk = 8 rows = 512 float4; thread t handles float4 t and t+256.
    // float4 f: row = f>>6 (0..7), col4 = f&63 (constant per thread).
    const int jc = (t & 63) * 4;
    const float w0 = sw[jc], w1 = sw[jc + 1], w2 = sw[jc + 2], w3 = sw[jc + 3];
    const int r0 = t >> 6;              // row of first float4 (0..3)
                                        // second float4 row = r0 + 4

    for (int b = 0; b < 8; ++b) {
        // ------------- phase 1: sync-free weighted reduction of x[b] -------------
        for (int ch = bid; ch < NCH; ch += GRID_G) {
            const int plane = ch >> 5, q = ch & 31;      // q: 8-row group
            const float4* __restrict__ p =
                (const float4*)x + ((size_t)(b * 256 + plane)) * PLANE4 + q * 512;
            const float4 va = __ldcg(p + t);
            const float4 vb = __ldcg(p + 256 + t);
            const float wa = sw[q * 8 + r0];
            const float wb = sw[q * 8 + r0 + 4];
            float acc = wa * (w0 * va.x + w1 * va.y + w2 * va.z + w3 * va.w)
                      + wb * (w0 * vb.x + w1 * vb.y + w2 * vb.z + w3 * vb.w);
#pragma unroll
            for (int o = 16; o; o >>= 1)
                acc += __shfl_down_sync(0xffffffffu, acc, o);
            if ((t & 31) == 0)
                atomicAdd(&g_yraw[b * 256 + plane], acc);    // RED.F32
        }

        // --------------------------- grid barrier (b) ---------------------------
        if (t == 0) {
            __threadfence();
            if (atomicAdd(&g_bar_count, 1) == GRID_G - 1) {
                atomicExch(&g_bar_count, 0);
                __threadfence();
                atomicExch(&g_bar_phase, b + 1);
            } else {
                while (atomicAdd(&g_bar_phase, 0) <= b) __nanosleep(64);
            }
        }
        __syncthreads();

        // ----------------- phase 2: FC (per block) + scale x[b] -----------------
        {
            const int u = t >> 4, k = t & 15;
            const float* w1p = W1 + u * 256 + k * 16;
            const float* yy = g_yraw + b * 256 + k * 16;
            float part = 0.f;
#pragma unroll
            for (int j = 0; j < 16; ++j) part += (yy[j] * INV_MEAN) * w1p[j];
            red[t] = part;
            __syncthreads();
            if (t < 16) {
                float s = 0.f;
#pragma unroll
                for (int j = 0; j < 16; ++j) s += red[t * 16 + j];
                sh_h[t] = fmaxf(s, 0.f);
            }
            __syncthreads();
        }

        for (int ch = bid; ch < NCH; ch += GRID_G) {
            const int plane = ch >> 5, q = ch & 31;
            float sv = 0.f;
            const float* w2p = W2 + plane * 16;
#pragma unroll
            for (int u = 0; u < 16; ++u) sv += sh_h[u] * w2p[u];
            sv = 1.f / (1.f + expf(-sv));

            const size_t base = ((size_t)(b * 256 + plane)) * PLANE4 + q * 512;
            const float4* __restrict__ px = (const float4*)x + base;
            float4* __restrict__ po = (float4*)out + base;
            float4 va = __ldcs(px + t);          // L2 hit, evict-first after
            float4 vb = __ldcs(px + 256 + t);
            va.x *= sv; va.y *= sv; va.z *= sv; va.w *= sv;
            vb.x *= sv; vb.y *= sv; vb.z *= sv; vb.w *= sv;
            __stcs(po + t, va);                  // streaming stores
            __stcs(po + 256 + t, vb);
        }
        __syncthreads();
        // no barrier: roll into reduce(b+1) so write(b) overlaps read(b+1)
    }
}

extern "C" void kernel_launch(void* const* d_in, const int* in_sizes, int n_in,
                              void* d_out, int out_size) {
    const float* x  = (const float*)d_in[0];
    const float* W1 = (const float*)d_in[1];   // [16,256]
    const float* W2 = (const float*)d_in[2];   // [256,16]
    float* out = (float*)d_out;

    init_kernel<<<8, 256>>>();
    fused_kernel<<<GRID_G, 256>>>(x, out, W1, W2);
}

// round 8
// speedup vs baseline: 1.1713x; 1.1713x over previous
#include <cuda_runtime.h>
#include <cuda_bf16.h>
#include <math.h>

// WaveletAttention: out = x * sigmoid(relu(mean(dwt2_ll(x)) @ W1^T) @ W2^T)
// x [8,256,256,256] f32 (512 MB), W1 [16,256], W2 [256,16].
//
// mean(dwt2_ll(x)) == (1/135^2) * sum_{i,j} w[i]*w[j]*x[b,c,i,j]  (linear +
// separable), w = fixed 256-weight vector from db8 dec_lo, symmetric pad.
//
// R8 = R7 with the block-reduction indexing bug fixed (warp partials live in
// red[0..7], not red[0],red[32],...) plus an acquire fence after the grid
// barrier before reading g_part with plain loads.
//
// Architecture: persistent kernel, strict per-batch phases (proven ~1.1 GB
// DRAM traffic). 512 blocks, 2 per plane, each owns a fixed 128 KB
// half-plane -> zero skew at the barrier. Reduce: 32 ld/thread, deep MLP,
// one block reduction, no atomics. Scale: ldcs (L2 hits) + stcs. No barrier
// after scale so write(b) overlaps read(b+1).

#define PLANE4   16384u        // float4 per 256x256 plane
#define INV_MEAN (1.0f/(135.0f*135.0f))

#define GRID_G   512           // 2 blocks/plane; co-resident at 4/SM
#define HALF4    8192          // float4 per half-plane
#define KIT      32            // float4 per thread per phase

__device__ float g_part[2][512];   // half-plane partials, batch-parity buffered
__device__ int   g_bar_count;
__device__ int   g_bar_phase;

// pywt db8 dec_lo, 16 taps
__constant__ float c_f[16] = {
    -0.00011747678400228192f, 0.0006754494059985568f, -0.0003917403729959771f,
    -0.00487035299301066f, 0.008746094047015655f, 0.013981027917015516f,
    -0.04408825393106472f, -0.01736930100202211f, 0.128747426620186f,
    0.00047248457399797254f, -0.2840155429624281f, -0.015829105256023893f,
    0.5853546836548691f, 0.6756307362980128f, 0.3128715909144659f,
    0.05441584224308161f
};

__device__ __forceinline__ float wcontrib(int q) {
    float s = 0.f;
#pragma unroll
    for (int k = 0; k < 16; ++k) {
        int qk = q + k;
        bool ok = ((qk & 1) == 0) && (qk >= 16) && (qk <= 284);
        s += ok ? c_f[k] : 0.f;
    }
    return s;
}
__device__ __forceinline__ float weight_at(int i) {
    return wcontrib(i + 15) + wcontrib(14 - i) + wcontrib(526 - i);
}

__global__ void init_kernel() {
    if (threadIdx.x == 0) { g_bar_count = 0; g_bar_phase = 0; }
}

__global__ void __launch_bounds__(256, 4)
fused_kernel(const float* __restrict__ x, float* __restrict__ out,
             const float* __restrict__ W1, const float* __restrict__ W2) {
    __shared__ float sw[256];
    __shared__ float red[256];
    __shared__ float sh_h[16];

    const int t = threadIdx.x;
    const int bid = blockIdx.x;
    const int plane = bid >> 1;          // 0..255
    const int half  = bid & 1;           // rows [half*128, half*128+128)

    sw[t] = weight_at(t);
    __syncthreads();

    // thread t covers float4 indices k*256 + t within its half-plane:
    //   row  = half*128 + k*4 + (t>>6),  col4 = (t&63)*4 (constant per thread)
    const int jc = (t & 63) * 4;
    const float w0 = sw[jc], w1 = sw[jc + 1], w2 = sw[jc + 2], w3 = sw[jc + 3];
    const int rbase = half * 128 + (t >> 6);

    for (int b = 0; b < 8; ++b) {
        const size_t base = ((size_t)(b * 256 + plane)) * PLANE4 + half * HALF4;

        // ----------- phase 1: weighted reduction of the half-plane -----------
        {
            const float4* __restrict__ p = (const float4*)x + base;
            float acc0 = 0.f, acc1 = 0.f;
#pragma unroll 4
            for (int k = 0; k < KIT; k += 2) {
                float4 va = p[k * 256 + t];          // evict-normal -> lands in L2
                float4 vb = p[(k + 1) * 256 + t];
                float wa = sw[rbase + k * 4];        // warp-uniform row weight
                float wb = sw[rbase + (k + 1) * 4];
                acc0 += wa * (w0 * va.x + w1 * va.y + w2 * va.z + w3 * va.w);
                acc1 += wb * (w0 * vb.x + w1 * vb.y + w2 * vb.z + w3 * vb.w);
            }
            float acc = acc0 + acc1;
#pragma unroll
            for (int o = 16; o; o >>= 1)
                acc += __shfl_down_sync(0xffffffffu, acc, o);
            if ((t & 31) == 0) red[t >> 5] = acc;    // warp partials -> red[0..7]
            __syncthreads();
            if (t == 0) {
                float v = red[0] + red[1] + red[2] + red[3]
                        + red[4] + red[5] + red[6] + red[7];   // FIXED indexing
                g_part[b & 1][plane * 2 + half] = v;
            }
        }

        // --------------------------- grid barrier ---------------------------
        if (t == 0) {
            __threadfence();
            if (atomicAdd(&g_bar_count, 1) == GRID_G - 1) {
                atomicExch(&g_bar_count, 0);
                __threadfence();
                atomicExch(&g_bar_phase, b + 1);
            } else {
                while (atomicAdd(&g_bar_phase, 0) <= b) __nanosleep(64);
            }
        }
        __syncthreads();
        __threadfence();                 // acquire: g_part stores visible

        // ---------------- phase 2: FC + scale the half-plane ----------------
        {
            // y[c] = (g_part[2c] + g_part[2c+1]) * INV_MEAN
            const float* gp = g_part[b & 1];
            const int u = t >> 4, k = t & 15;        // h[u]: 16 partials each
            const float* w1p = W1 + u * 256 + k * 16;
            float part = 0.f;
#pragma unroll
            for (int j = 0; j < 16; ++j) {
                const int c = k * 16 + j;
                part += (gp[2 * c] + gp[2 * c + 1]) * INV_MEAN * w1p[j];
            }
            red[t] = part;
            __syncthreads();
            if (t < 16) {
                float s = 0.f;
#pragma unroll
                for (int j = 0; j < 16; ++j) s += red[t * 16 + j];
                sh_h[t] = fmaxf(s, 0.f);
            }
            __syncthreads();

            float sv = 0.f;
            const float* w2p = W2 + plane * 16;
#pragma unroll
            for (int u2 = 0; u2 < 16; ++u2) sv += sh_h[u2] * w2p[u2];
            sv = 1.f / (1.f + expf(-sv));

            const float4* __restrict__ px = (const float4*)x + base;
            float4* __restrict__ po = (float4*)out + base;
#pragma unroll 4
            for (int k2 = 0; k2 < KIT; ++k2) {
                float4 v = __ldcs(px + k2 * 256 + t);   // L2 hit, evict-first
                v.x *= sv; v.y *= sv; v.z *= sv; v.w *= sv;
                __stcs(po + k2 * 256 + t, v);           // streaming store
            }
        }
        __syncthreads();
        // no barrier here: roll into reduce(b+1); write(b) overlaps read(b+1)
    }
}

extern "C" void kernel_launch(void* const* d_in, const int* in_sizes, int n_in,
                              void* d_out, int out_size) {
    const float* x  = (const float*)d_in[0];
    const float* W1 = (const float*)d_in[1];   // [16,256]
    const float* W2 = (const float*)d_in[2];   // [256,16]
    float* out = (float*)d_out;

    init_kernel<<<1, 32>>>();
    fused_kernel<<<GRID_G, 256>>>(x, out, W1, W2);
}

// round 9
// speedup vs baseline: 1.5905x; 1.3579x over previous
#include <cuda_runtime.h>
#include <cuda_bf16.h>
#include <math.h>

// WaveletAttention: out = x * sigmoid(relu(mean(dwt2_ll(x)) @ W1^T) @ W2^T)
// x [8,256,256,256] f32 (512 MB), W1 [16,256], W2 [256,16].
//
// mean(dwt2_ll(x)) == (1/135^2) * sum_{i,j} w[i]*w[j]*x[b,c,i,j]  (linear +
// separable), w = fixed 256-weight vector from db8 dec_lo, symmetric pad.
//
// R9: back to the proven 3-kernel streaming structure (R1, 260 us; the
// persistent L2-reuse family capped at 33-53% DRAM five rounds running).
// Reduce kernel unchanged (measured 6.6 TB/s = ceiling). Scale kernel
// rebuilt for the mixed read+write stream: 8 outstanding ldcs per thread
// before any store, stcs streaming writes, 512-thread blocks.

#define PLANE4   16384         // float4 per 256x256 plane
#define NBC      2048
#define INV_MEAN (1.0f/(135.0f*135.0f))

__device__ float g_y[NBC];     // weighted spatial means
__device__ float g_s[NBC];     // channel scales (sigmoid output)

// pywt db8 dec_lo, 16 taps
__constant__ float c_f[16] = {
    -0.00011747678400228192f, 0.0006754494059985568f, -0.0003917403729959771f,
    -0.00487035299301066f, 0.008746094047015655f, 0.013981027917015516f,
    -0.04408825393106472f, -0.01736930100202211f, 0.128747426620186f,
    0.00047248457399797254f, -0.2840155429624281f, -0.015829105256023893f,
    0.5853546836548691f, 0.6756307362980128f, 0.3128715909144659f,
    0.05441584224308161f
};

__device__ __forceinline__ float wcontrib(int q) {
    float s = 0.f;
#pragma unroll
    for (int k = 0; k < 16; ++k) {
        int qk = q + k;
        bool ok = ((qk & 1) == 0) && (qk >= 16) && (qk <= 284);
        s += ok ? c_f[k] : 0.f;
    }
    return s;
}
__device__ __forceinline__ float weight_at(int i) {
    return wcontrib(i + 15) + wcontrib(14 - i) + wcontrib(526 - i);
}

// ---------------------------------------------------------------------------
// Kernel 1: per-(b,c) weighted spatial reduction. One block per plane.
// Measured 6.6 TB/s in R1 — at the read-stream ceiling.
// ---------------------------------------------------------------------------
__global__ void __launch_bounds__(256) reduce_kernel(const float* __restrict__ x) {
    __shared__ float sw[256];
    __shared__ float red[8];
    const int t = threadIdx.x;

    sw[t] = weight_at(t);
    __syncthreads();

    const int bc = blockIdx.x;
    const float4* __restrict__ p = (const float4*)x + (size_t)bc * PLANE4;

    const int jc = (t & 63) * 4;
    const float w0 = sw[jc + 0], w1 = sw[jc + 1], w2 = sw[jc + 2], w3 = sw[jc + 3];
    const int ibase = t >> 6;

    float acc = 0.f;
#pragma unroll 8
    for (int it = 0; it < 64; ++it) {
        float4 v = __ldcg(p + it * 256 + t);      // skip L1, no reuse
        float wi = sw[ibase + it * 4];
        acc += wi * (w0 * v.x + w1 * v.y + w2 * v.z + w3 * v.w);
    }

#pragma unroll
    for (int o = 16; o; o >>= 1) acc += __shfl_down_sync(0xffffffffu, acc, o);
    if ((t & 31) == 0) red[t >> 5] = acc;
    __syncthreads();
    if (t < 8) {
        float v = red[t];
#pragma unroll
        for (int o = 4; o; o >>= 1) v += __shfl_down_sync(0xffu, v, o);
        if (t == 0) g_y[bc] = v * INV_MEAN;
    }
}

// ---------------------------------------------------------------------------
// Kernel 2: tiny FC  y[8,256] -> relu(y@W1^T)[8,16] -> sigmoid(h@W2^T)[8,256]
// ---------------------------------------------------------------------------
__global__ void __launch_bounds__(256) fc_kernel(const float* __restrict__ W1,
                                                 const float* __restrict__ W2) {
    __shared__ float sh[128];      // h[b,u], 8*16
    const int t = threadIdx.x;
    if (t < 128) {
        const int b = t >> 4, u = t & 15;
        const float* yb = g_y + b * 256;
        const float* w1 = W1 + u * 256;
        float s = 0.f;
#pragma unroll 8
        for (int c = 0; c < 256; ++c) s += yb[c] * w1[c];
        sh[t] = fmaxf(s, 0.f);
    }
    __syncthreads();
#pragma unroll
    for (int r = 0; r < 8; ++r) {
        const int o = r * 256 + t;
        const int b = o >> 8, c = o & 255;
        float s = 0.f;
#pragma unroll
        for (int u = 0; u < 16; ++u) s += sh[b * 16 + u] * W2[c * 16 + u];
        g_s[o] = 1.f / (1.f + expf(-s));
    }
}

// ---------------------------------------------------------------------------
// Kernel 3: out = x * s[b,c]. grid (4, 2048), 512 threads, 8 float4/thread.
// All 8 loads issued (ldcs, MLP=8) before the 8 streaming stores.
// ---------------------------------------------------------------------------
__global__ void __launch_bounds__(512) scale_kernel(const float* __restrict__ x,
                                                    float* __restrict__ out) {
    const int bc = blockIdx.y;
    const float s = g_s[bc];
    const size_t base = (size_t)bc * PLANE4 + blockIdx.x * 4096 + threadIdx.x;
    const float4* __restrict__ px = (const float4*)x + base;
    float4* __restrict__ po = (float4*)out + base;

    float4 v[8];
#pragma unroll
    for (int k = 0; k < 8; ++k) v[k] = __ldcs(px + k * 512);   // 8 outstanding
#pragma unroll
    for (int k = 0; k < 8; ++k) {
        v[k].x *= s; v[k].y *= s; v[k].z *= s; v[k].w *= s;
        __stcs(po + k * 512, v[k]);                            // streaming store
    }
}

extern "C" void kernel_launch(void* const* d_in, const int* in_sizes, int n_in,
                              void* d_out, int out_size) {
    const float* x  = (const float*)d_in[0];
    const float* W1 = (const float*)d_in[1];   // [16,256]
    const float* W2 = (const float*)d_in[2];   // [256,16]
    float* out = (float*)d_out;

    reduce_kernel<<<NBC, 256>>>(x);
    fc_kernel<<<1, 256>>>(W1, W2);
    scale_kernel<<<dim3(4, NBC), 512>>>(x, out);
}

// round 10
// speedup vs baseline: 1.6081x; 1.0111x over previous
#include <cuda_runtime.h>
#include <cuda_bf16.h>
#include <math.h>

// WaveletAttention: out = x * sigmoid(relu(mean(dwt2_ll(x)) @ W1^T) @ W2^T)
// x [8,256,256,256] f32 (512 MB), W1 [16,256], W2 [256,16].
//
// mean(dwt2_ll(x)) == (1/135^2) * sum_{i,j} w[i]*w[j]*x[b,c,i,j]  (linear +
// separable), w = fixed 256-weight vector from db8 dec_lo, symmetric pad.
//
// R10 = R9 (proven 3-kernel streaming; reduce at 6.83 TB/s ceiling) plus:
//  1. scale processes planes in REVERSE order: the ~110 MB tail of x that
//     reduce just pulled into L2 is read back as L2 hits by scale's first
//     waves (block scheduler issues ascending blockIdx).
//  2. FC fused into the scale kernel (per-block redundant, R2-verified),
//     removing the fc launch.

#define PLANE4   16384         // float4 per 256x256 plane
#define NBC      2048
#define INV_MEAN (1.0f/(135.0f*135.0f))

__device__ float g_y[NBC];     // weighted spatial means

// pywt db8 dec_lo, 16 taps
__constant__ float c_f[16] = {
    -0.00011747678400228192f, 0.0006754494059985568f, -0.0003917403729959771f,
    -0.00487035299301066f, 0.008746094047015655f, 0.013981027917015516f,
    -0.04408825393106472f, -0.01736930100202211f, 0.128747426620186f,
    0.00047248457399797254f, -0.2840155429624281f, -0.015829105256023893f,
    0.5853546836548691f, 0.6756307362980128f, 0.3128715909144659f,
    0.05441584224308161f
};

__device__ __forceinline__ float wcontrib(int q) {
    float s = 0.f;
#pragma unroll
    for (int k = 0; k < 16; ++k) {
        int qk = q + k;
        bool ok = ((qk & 1) == 0) && (qk >= 16) && (qk <= 284);
        s += ok ? c_f[k] : 0.f;
    }
    return s;
}
__device__ __forceinline__ float weight_at(int i) {
    return wcontrib(i + 15) + wcontrib(14 - i) + wcontrib(526 - i);
}

// ---------------------------------------------------------------------------
// Kernel 1: per-(b,c) weighted spatial reduction. One block per plane.
// 6.83 TB/s measured — read-stream ceiling. Loads evict-normal so the tail
// of x stays resident in L2 for the scale kernel.
// ---------------------------------------------------------------------------
__global__ void __launch_bounds__(256) reduce_kernel(const float* __restrict__ x) {
    __shared__ float sw[256];
    __shared__ float red[8];
    const int t = threadIdx.x;

    sw[t] = weight_at(t);
    __syncthreads();

    const int bc = blockIdx.x;
    const float4* __restrict__ p = (const float4*)x + (size_t)bc * PLANE4;

    const int jc = (t & 63) * 4;
    const float w0 = sw[jc + 0], w1 = sw[jc + 1], w2 = sw[jc + 2], w3 = sw[jc + 3];
    const int ibase = t >> 6;

    float acc = 0.f;
#pragma unroll 8
    for (int it = 0; it < 64; ++it) {
        float4 v = __ldcg(p + it * 256 + t);      // L2-allocating, skip L1
        float wi = sw[ibase + it * 4];
        acc += wi * (w0 * v.x + w1 * v.y + w2 * v.z + w3 * v.w);
    }

#pragma unroll
    for (int o = 16; o; o >>= 1) acc += __shfl_down_sync(0xffffffffu, acc, o);
    if ((t & 31) == 0) red[t >> 5] = acc;
    __syncthreads();
    if (t < 8) {
        float v = red[t];
#pragma unroll
        for (int o = 4; o; o >>= 1) v += __shfl_down_sync(0xffu, v, o);
        if (t == 0) g_y[bc] = v * INV_MEAN;
    }
}

// ---------------------------------------------------------------------------
// Kernel 2: fused FC + scale. Grid 8192 x 256 thr; 16 float4/thread.
// bc runs DESCENDING in blockIdx so the first waves hit the L2-resident
// tail of x left by reduce. Inline FC is redundant per block (cheap).
// ---------------------------------------------------------------------------
__global__ void __launch_bounds__(256) scale_kernel(const float* __restrict__ x,
                                                    float* __restrict__ out,
                                                    const float* __restrict__ W1,
                                                    const float* __restrict__ W2) {
    __shared__ float red[256];
    __shared__ float sh_h[16];

    const int t = threadIdx.x;
    const int bid = blockIdx.x;
    const int bc = (NBC - 1) - (bid >> 2);   // reverse plane order
    const int chunk = bid & 3;
    const int b = bc >> 8, c = bc & 255;

    // ---- inline FC: h[u] = relu(sum_c y[b,c]*W1[u,c]); s = sigmoid(h.W2[c]) ----
    {
        const float* yb = g_y + b * 256;
        const int u = t >> 4, k = t & 15;
        const float* w1p = W1 + u * 256 + k * 16;
        const float* yy = yb + k * 16;
        float part = 0.f;
#pragma unroll
        for (int j = 0; j < 16; ++j) part += yy[j] * w1p[j];
        red[t] = part;
        __syncthreads();
        if (t < 16) {
            float s = 0.f;
#pragma unroll
            for (int j = 0; j < 16; ++j) s += red[t * 16 + j];
            sh_h[t] = fmaxf(s, 0.f);
        }
        __syncthreads();
    }
    float sv = 0.f;
    {
        const float* w2p = W2 + c * 16;
#pragma unroll
        for (int u = 0; u < 16; ++u) sv += sh_h[u] * w2p[u];
        sv = 1.f / (1.f + expf(-sv));
    }

    const size_t base = (size_t)bc * PLANE4 + chunk * 4096 + t;
    const float4* __restrict__ px = (const float4*)x + base;
    float4* __restrict__ po = (float4*)out + base;

#pragma unroll
    for (int k = 0; k < 16; k += 8) {
        float4 v[8];
#pragma unroll
        for (int j = 0; j < 8; ++j) v[j] = __ldcs(px + (k + j) * 256);
#pragma unroll
        for (int j = 0; j < 8; ++j) {
            v[j].x *= sv; v[j].y *= sv; v[j].z *= sv; v[j].w *= sv;
            __stcs(po + (k + j) * 256, v[j]);
        }
    }
}

extern "C" void kernel_launch(void* const* d_in, const int* in_sizes, int n_in,
                              void* d_out, int out_size) {
    const float* x  = (const float*)d_in[0];
    const float* W1 = (const float*)d_in[1];   // [16,256]
    const float* W2 = (const float*)d_in[2];   // [256,16]
    float* out = (float*)d_out;

    reduce_kernel<<<NBC, 256>>>(x);
    scale_kernel<<<NBC * 4, 256>>>(x, out, W1, W2);
}

// round 12
// speedup vs baseline: 1.6372x; 1.0181x over previous
#include <cuda_runtime.h>
#include <cuda_bf16.h>
#include <math.h>

// WaveletAttention: out = x * sigmoid(relu(mean(dwt2_ll(x)) @ W1^T) @ W2^T)
// x [8,256,256,256] f32 (512 MB), W1 [16,256], W2 [256,16].
//
// mean(dwt2_ll(x)) == (1/135^2) * sum_{i,j} w[i]*w[j]*x[b,c,i,j]  (linear +
// separable), w = fixed 256-weight vector from db8 dec_lo, symmetric pad.
//
// R12 = R10 (2-kernel streaming + reverse-order L2 tail harvest, 257.7 us)
// with deliberate L2 eviction policy in reduce:
//   planes bc <  1600: ld.cs (evict-first) — never reusable, keep L2 clean
//   planes bc >= 1600: ld.global.L2::evict_last.v4.b64 (32B loads; the only
//   encodable form on sm_103) — pin the 112 MB tail that scale (reverse
//   order) reads first as L2 hits.

#define PLANE      65536       // floats per 256x256 plane
#define PLANE4     16384       // float4 per plane
#define NBC        2048
#define INV_MEAN   (1.0f/(135.0f*135.0f))
#define TAIL_START 1600        // 448 pinned planes = 112 MB (L2 = 126 MB)

__device__ float g_y[NBC];     // weighted spatial means

// pywt db8 dec_lo, 16 taps
__constant__ float c_f[16] = {
    -0.00011747678400228192f, 0.0006754494059985568f, -0.0003917403729959771f,
    -0.00487035299301066f, 0.008746094047015655f, 0.013981027917015516f,
    -0.04408825393106472f, -0.01736930100202211f, 0.128747426620186f,
    0.00047248457399797254f, -0.2840155429624281f, -0.015829105256023893f,
    0.5853546836548691f, 0.6756307362980128f, 0.3128715909144659f,
    0.05441584224308161f
};

__device__ __forceinline__ float wcontrib(int q) {
    float s = 0.f;
#pragma unroll
    for (int k = 0; k < 16; ++k) {
        int qk = q + k;
        bool ok = ((qk & 1) == 0) && (qk >= 16) && (qk <= 284);
        s += ok ? c_f[k] : 0.f;
    }
    return s;
}
__device__ __forceinline__ float weight_at(int i) {
    return wcontrib(i + 15) + wcontrib(14 - i) + wcontrib(526 - i);
}

// 32-byte (8-float) load pinned to L2 with evict_last. 32B-aligned address.
__device__ __forceinline__ void ldg_el8(const float* p, float* v) {
    unsigned long long x0, x1, x2, x3;
    asm volatile("ld.global.L2::evict_last.v4.b64 {%0,%1,%2,%3}, [%4];"
                 : "=l"(x0), "=l"(x1), "=l"(x2), "=l"(x3) : "l"(p));
    v[0] = __uint_as_float((unsigned)x0); v[1] = __uint_as_float((unsigned)(x0 >> 32));
    v[2] = __uint_as_float((unsigned)x1); v[3] = __uint_as_float((unsigned)(x1 >> 32));
    v[4] = __uint_as_float((unsigned)x2); v[5] = __uint_as_float((unsigned)(x2 >> 32));
    v[6] = __uint_as_float((unsigned)x3); v[7] = __uint_as_float((unsigned)(x3 >> 32));
}

// ---------------------------------------------------------------------------
// Kernel 1: per-(b,c) weighted spatial reduction. One block per plane.
// Head planes evict-first; tail planes pinned evict-last (32B loads).
// ---------------------------------------------------------------------------
__global__ void __launch_bounds__(256) reduce_kernel(const float* __restrict__ x) {
    __shared__ float sw[256];
    __shared__ float red[8];
    const int t = threadIdx.x;

    sw[t] = weight_at(t);
    __syncthreads();

    const int bc = blockIdx.x;
    float acc = 0.f;

    if (bc >= TAIL_START) {
        // 32B per thread per iter: floats [it*2048 + t*8, +8)
        //   row = it*8 + (t>>5)  (warp-uniform), cols = (t&31)*8 .. +7
        const float* __restrict__ pf = x + (size_t)bc * PLANE;
        const int cb = (t & 31) * 8;
        float wc[8];
#pragma unroll
        for (int j = 0; j < 8; ++j) wc[j] = sw[cb + j];
        const int rbase = t >> 5;
#pragma unroll 4
        for (int it = 0; it < 32; ++it) {
            float v[8];
            ldg_el8(pf + it * 2048 + t * 8, v);      // pin in L2
            float wi = sw[it * 8 + rbase];
            float d = wc[0] * v[0] + wc[1] * v[1] + wc[2] * v[2] + wc[3] * v[3]
                    + wc[4] * v[4] + wc[5] * v[5] + wc[6] * v[6] + wc[7] * v[7];
            acc += wi * d;
        }
    } else {
        // float4 per thread per iter: row = it*4 + (t>>6), cols = (t&63)*4..+3
        const float4* __restrict__ p = (const float4*)x + (size_t)bc * PLANE4;
        const int jc = (t & 63) * 4;
        const float w0 = sw[jc], w1 = sw[jc + 1], w2 = sw[jc + 2], w3 = sw[jc + 3];
        const int ibase = t >> 6;
#pragma unroll 8
        for (int it = 0; it < 64; ++it) {
            float4 v = __ldcs(p + it * 256 + t);     // evict-first
            float wi = sw[ibase + it * 4];
            acc += wi * (w0 * v.x + w1 * v.y + w2 * v.z + w3 * v.w);
        }
    }

#pragma unroll
    for (int o = 16; o; o >>= 1) acc += __shfl_down_sync(0xffffffffu, acc, o);
    if ((t & 31) == 0) red[t >> 5] = acc;
    __syncthreads();
    if (t < 8) {
        float v = red[t];
#pragma unroll
        for (int o = 4; o; o >>= 1) v += __shfl_down_sync(0xffu, v, o);
        if (t == 0) g_y[bc] = v * INV_MEAN;
    }
}

// ---------------------------------------------------------------------------
// Kernel 2: fused FC + scale. Grid 8192 x 256 thr; 16 float4/thread.
// bc DESCENDING in blockIdx: first waves consume the pinned L2 tail.
// ---------------------------------------------------------------------------
__global__ void __launch_bounds__(256) scale_kernel(const float* __restrict__ x,
                                                    float* __restrict__ out,
                                                    const float* __restrict__ W1,
                                                    const float* __restrict__ W2) {
    __shared__ float red[256];
    __shared__ float sh_h[16];

    const int t = threadIdx.x;
    const int bid = blockIdx.x;
    const int bc = (NBC - 1) - (bid >> 2);   // reverse plane order
    const int chunk = bid & 3;
    const int b = bc >> 8, c = bc & 255;

    // ---- inline FC: h[u] = relu(sum_c y[b,c]*W1[u,c]); s = sigmoid(h.W2[c]) ----
    {
        const float* yb = g_y + b * 256;
        const int u = t >> 4, k = t & 15;
        const float* w1p = W1 + u * 256 + k * 16;
        const float* yy = yb + k * 16;
        float part = 0.f;
#pragma unroll
        for (int j = 0; j < 16; ++j) part += yy[j] * w1p[j];
        red[t] = part;
        __syncthreads();
        if (t < 16) {
            float s = 0.f;
#pragma unroll
            for (int j = 0; j < 16; ++j) s += red[t * 16 + j];
            sh_h[t] = fmaxf(s, 0.f);
        }
        __syncthreads();
    }
    float sv = 0.f;
    {
        const float* w2p = W2 + c * 16;
#pragma unroll
        for (int u = 0; u < 16; ++u) sv += sh_h[u] * w2p[u];
        sv = 1.f / (1.f + expf(-sv));
    }

    const size_t base = (size_t)bc * PLANE4 + chunk * 4096 + t;
    const float4* __restrict__ px = (const float4*)x + base;
    float4* __restrict__ po = (float4*)out + base;

#pragma unroll
    for (int k = 0; k < 16; k += 8) {
        float4 v[8];
#pragma unroll
        for (int j = 0; j < 8; ++j) v[j] = __ldcs(px + (k + j) * 256);
#pragma unroll
        for (int j = 0; j < 8; ++j) {
            v[j].x *= sv; v[j].y *= sv; v[j].z *= sv; v[j].w *= sv;
            __stcs(po + (k + j) * 256, v[j]);
        }
    }
}

extern "C" void kernel_launch(void* const* d_in, const int* in_sizes, int n_in,
                              void* d_out, int out_size) {
    const float* x  = (const float*)d_in[0];
    const float* W1 = (const float*)d_in[1];   // [16,256]
    const float* W2 = (const float*)d_in[2];   // [256,16]
    float* out = (float*)d_out;

    reduce_kernel<<<NBC, 256>>>(x);
    scale_kernel<<<NBC * 4, 256>>>(x, out, W1, W2);
}